// round 5
// baseline (speedup 1.0000x reference)
#include <cuda_runtime.h>
#include <cuda_bf16.h>
#include <cstdint>

#define D 128
#define NMAX 50000
#define EMAX 800000
#define D4 (D/4)   // 32 float4 per row
#define D2 (D/2)   // 64 float2 per row

// ---------------- scratch (no allocations allowed) ----------------
__device__ int   g_deg[NMAX];          // 1 + in-degree (self-loop included)
__device__ float g_dinv[NMAX];
__device__ int   g_rowstart[NMAX];     // CSR row offsets (real edges only)
__device__ int   g_cur[NMAX];          // absolute fill cursors
__device__ int   g_esrc[EMAX];         // CSR: src node per slot
__device__ float g_enorm[EMAX];        // CSR: dinv[src]*dinv[dst] per slot
__device__ float g_h[(size_t)NMAX * D];   // linear-transform output
__device__ float g_a[(size_t)NMAX * D];   // layer-1 activation
__device__ int   g_is64;               // 1 if edge_index is int64, 0 if int32

__device__ __forceinline__ int load_idx(const int* __restrict__ ei, size_t pos) {
    return g_is64 ? ei[2 * pos] : ei[pos];
}

// ---------------- init degrees + dtype detect (fused) ----------------
__global__ void k_init(const int* __restrict__ ei, int n) {
    int i = blockIdx.x * blockDim.x + threadIdx.x;
    if (i < n) g_deg[i] = 1;              // self-loop contributes 1
    if (blockIdx.x == 0 && threadIdx.x == 0) {
        // int64 edge_index (values < 2^31) => every odd 32-bit word is 0
        int all0 = 1;
        for (int j = 0; j < 64; ++j)
            if (ei[2 * j + 1] != 0) { all0 = 0; break; }
        g_is64 = all0;
    }
}

__global__ void k_count(const int* __restrict__ ei, int E) {
    int e = blockIdx.x * blockDim.x + threadIdx.x;
    if (e < E) atomicAdd(&g_deg[load_idx(ei, (size_t)E + e)], 1);
}

// ---------------- scan of (deg-1) -> rowstart; abs cursors; dinv (fused) --
__global__ void k_scan(int n) {
    __shared__ int part[1024];
    const int tid = threadIdx.x;
    const int chunk = (n + 1023) / 1024;
    const int beg = tid * chunk;
    const int end = min(beg + chunk, n);

    int s = 0;
    for (int i = beg; i < end; ++i) s += g_deg[i] - 1;
    part[tid] = s;
    __syncthreads();

    for (int off = 1; off < 1024; off <<= 1) {
        int v = (tid >= off) ? part[tid - off] : 0;
        __syncthreads();
        part[tid] += v;
        __syncthreads();
    }

    int run = (tid > 0) ? part[tid - 1] : 0;
    for (int i = beg; i < end; ++i) {
        int dg = g_deg[i];
        g_rowstart[i] = run;
        g_cur[i] = run;                      // absolute cursor
        g_dinv[i] = rsqrtf((float)dg);
        run += dg - 1;
    }
}

// ---------------- CSR fill (absolute cursor: one atomic, no extra load) ---
__global__ void k_fill(const int* __restrict__ ei, int E) {
    int e = blockIdx.x * blockDim.x + threadIdx.x;
    if (e >= E) return;
    int s = load_idx(ei, (size_t)e);
    int d = load_idx(ei, (size_t)E + e);
    int pos = atomicAdd(&g_cur[d], 1);
    g_esrc[pos]  = s;
    g_enorm[pos] = g_dinv[s] * g_dinv[d];
}

// ---------------- GEMM: C[M,128] = A[M,128] @ W[128,128] (R3 FFMA4) -------
#define FMA4(acc, s, b) { acc.x = fmaf(s, b.x, acc.x); acc.y = fmaf(s, b.y, acc.y); \
                          acc.z = fmaf(s, b.z, acc.z); acc.w = fmaf(s, b.w, acc.w); }

__global__ void k_gemm(const float* __restrict__ A, const float* __restrict__ Wm,
                       float* __restrict__ C, int M) {
    int lane = threadIdx.x & 31;
    int rs   = threadIdx.x >> 5;
    int row0 = blockIdx.x * 32 + rs * 4;
    if (row0 >= M) return;

    const float4* A4 = (const float4*)A;
    const float4* W4 = (const float4*)Wm;

    float4 acc0 = make_float4(0,0,0,0), acc1 = acc0, acc2 = acc0, acc3 = acc0;

    size_t ar0 = (size_t)(row0 + 0) * D4;
    size_t ar1 = (size_t)(row0 + 1) * D4;
    size_t ar2 = (size_t)(row0 + 2) * D4;
    size_t ar3 = (size_t)(row0 + 3) * D4;

#pragma unroll 4
    for (int k4 = 0; k4 < D4; ++k4) {
        float4 a0 = A4[ar0 + k4];
        float4 a1 = A4[ar1 + k4];
        float4 a2 = A4[ar2 + k4];
        float4 a3 = A4[ar3 + k4];
        int k = k4 * 4;
        float4 b0 = W4[(size_t)(k + 0) * D4 + lane];
        float4 b1 = W4[(size_t)(k + 1) * D4 + lane];
        float4 b2 = W4[(size_t)(k + 2) * D4 + lane];
        float4 b3 = W4[(size_t)(k + 3) * D4 + lane];

        FMA4(acc0, a0.x, b0); FMA4(acc0, a0.y, b1); FMA4(acc0, a0.z, b2); FMA4(acc0, a0.w, b3);
        FMA4(acc1, a1.x, b0); FMA4(acc1, a1.y, b1); FMA4(acc1, a1.z, b2); FMA4(acc1, a1.w, b3);
        FMA4(acc2, a2.x, b0); FMA4(acc2, a2.y, b1); FMA4(acc2, a2.z, b2); FMA4(acc2, a2.w, b3);
        FMA4(acc3, a3.x, b0); FMA4(acc3, a3.y, b1); FMA4(acc3, a3.z, b2); FMA4(acc3, a3.w, b3);
    }

    float4* C4 = (float4*)C;
    C4[ar0 + lane] = acc0;
    C4[ar1 + lane] = acc1;
    C4[ar2 + lane] = acc2;
    C4[ar3 + lane] = acc3;
}

// ---------------- CSR aggregation + self-loop + bias + ReLU --------------
// TWO warps per dst node; each warp owns half the row (64 floats), lane owns
// one float2. Same L2 traffic, 2x edge-level parallelism vs warp-per-node.
#define FMA2v(acc, s, b) { acc.x = fmaf(s, b.x, acc.x); acc.y = fmaf(s, b.y, acc.y); }

__global__ void k_agg_csr(const float* __restrict__ H,
                          const float* __restrict__ b,
                          float* __restrict__ out, int n) {
    int gw   = (int)((blockIdx.x * (size_t)blockDim.x + threadIdx.x) >> 5);
    int lane = threadIdx.x & 31;
    int node = gw >> 1;
    int half = gw & 1;
    if (node >= n) return;

    const float2* H2 = (const float2*)H;
    int col = half * 32 + lane;            // float2 index within the row (0..63)

    float di = g_dinv[node];
    float sl = di * di;

    float2 acc = H2[(size_t)node * D2 + col];   // self-loop
    acc.x *= sl; acc.y *= sl;

    int p   = g_rowstart[node];
    int end = p + (g_deg[node] - 1);

    for (; p + 3 < end; p += 4) {
        int   s0 = g_esrc[p],   s1 = g_esrc[p+1], s2 = g_esrc[p+2], s3 = g_esrc[p+3];
        float n0 = g_enorm[p],  n1 = g_enorm[p+1], n2 = g_enorm[p+2], n3 = g_enorm[p+3];
        float2 v0 = H2[(size_t)s0 * D2 + col];
        float2 v1 = H2[(size_t)s1 * D2 + col];
        float2 v2 = H2[(size_t)s2 * D2 + col];
        float2 v3 = H2[(size_t)s3 * D2 + col];
        FMA2v(acc, n0, v0);
        FMA2v(acc, n1, v1);
        FMA2v(acc, n2, v2);
        FMA2v(acc, n3, v3);
    }
    for (; p < end; ++p) {
        int   s0 = g_esrc[p];
        float n0 = g_enorm[p];
        float2 v0 = H2[(size_t)s0 * D2 + col];
        FMA2v(acc, n0, v0);
    }

    float2 bv = ((const float2*)b)[col];
    float2 r;
    r.x = fmaxf(acc.x + bv.x, 0.f);
    r.y = fmaxf(acc.y + bv.y, 0.f);
    ((float2*)out)[(size_t)node * D2 + col] = r;
}

// ---------------- launch ----------------
extern "C" void kernel_launch(void* const* d_in, const int* in_sizes, int n_in,
                              void* d_out, int out_size) {
    const float* x  = (const float*)d_in[0];
    const int*   ei = (const int*)d_in[1];
    const float* W1 = (const float*)d_in[2];
    const float* b1 = (const float*)d_in[3];
    const float* W2 = (const float*)d_in[4];
    const float* b2 = (const float*)d_in[5];
    float* out = (float*)d_out;

    int n = in_sizes[0] / D;        // 50000
    int E = in_sizes[1] / 2;        // 800000

    float *h, *a;
    cudaGetSymbolAddress((void**)&h, g_h);
    cudaGetSymbolAddress((void**)&a, g_a);

    // ---- setup: degrees+detect, count, scan(+dinv+cursors), CSR fill ----
    k_init<<<(n + 255) / 256, 256>>>(ei, n);
    k_count<<<(E + 255) / 256, 256>>>(ei, E);
    k_scan<<<1, 1024>>>(n);
    k_fill<<<(E + 255) / 256, 256>>>(ei, E);

    int aggBlocks = (n * 64 + 255) / 256;   // 2 warps per node

    // ---- layer 1 ----
    k_gemm<<<(n + 31) / 32, 256>>>(x, W1, h, n);
    k_agg_csr<<<aggBlocks, 256>>>(h, b1, a, n);

    // ---- layer 2 ----
    k_gemm<<<(n + 31) / 32, 256>>>(a, W2, h, n);
    k_agg_csr<<<aggBlocks, 256>>>(h, b2, out, n);
}

// round 6
// speedup vs baseline: 1.0758x; 1.0758x over previous
#include <cuda_runtime.h>
#include <cuda_bf16.h>
#include <cstdint>

#define D 128
#define NMAX 50000
#define EMAX 800000
#define D4 (D/4)   // 32 float4 per row

// ---------------- scratch (no allocations allowed) ----------------
__device__ int   g_deg[NMAX];          // 1 + in-degree (self-loop included)
__device__ float g_dinv[NMAX];
__device__ int   g_rowstart[NMAX];     // CSR row offsets (real edges only)
__device__ int   g_cur[NMAX];          // absolute fill cursors
__device__ int   g_esrc[EMAX];         // CSR: src node per slot
__device__ float g_h[(size_t)NMAX * D];   // linear-transform output
__device__ float g_a[(size_t)NMAX * D];   // layer-1 activation
__device__ int   g_is64;               // 1 if edge_index is int64, 0 if int32

__device__ __forceinline__ int load_idx(const int* __restrict__ ei, size_t pos) {
    return g_is64 ? ei[2 * pos] : ei[pos];
}

// ---------------- init degrees + dtype detect (fused) ----------------
__global__ void k_init(const int* __restrict__ ei, int n) {
    int i = blockIdx.x * blockDim.x + threadIdx.x;
    if (i < n) g_deg[i] = 1;              // self-loop contributes 1
    if (blockIdx.x == 0 && threadIdx.x == 0) {
        // int64 edge_index (values < 2^31) => every odd 32-bit word is 0
        int all0 = 1;
        for (int j = 0; j < 64; ++j)
            if (ei[2 * j + 1] != 0) { all0 = 0; break; }
        g_is64 = all0;
    }
}

// ---------------- GEMM body (shared by mega + gemm2) ----------------
#define FMA4(acc, s, b) { acc.x = fmaf(s, b.x, acc.x); acc.y = fmaf(s, b.y, acc.y); \
                          acc.z = fmaf(s, b.z, acc.z); acc.w = fmaf(s, b.w, acc.w); }

// SCALE_OUT: multiply output row r by g_dinv[r] in the epilogue.
template<bool SCALE_OUT>
__device__ __forceinline__ void gemm_body(int bid, int tid,
                                          const float* __restrict__ A,
                                          const float* __restrict__ Wm,
                                          float* __restrict__ C, int M) {
    int lane = tid & 31;
    int rs   = tid >> 5;
    int row0 = bid * 32 + rs * 4;
    if (row0 >= M) return;

    const float4* A4 = (const float4*)A;
    const float4* W4 = (const float4*)Wm;

    float4 acc0 = make_float4(0,0,0,0), acc1 = acc0, acc2 = acc0, acc3 = acc0;

    size_t ar0 = (size_t)(row0 + 0) * D4;
    size_t ar1 = (size_t)(row0 + 1) * D4;
    size_t ar2 = (size_t)(row0 + 2) * D4;
    size_t ar3 = (size_t)(row0 + 3) * D4;

#pragma unroll 4
    for (int k4 = 0; k4 < D4; ++k4) {
        float4 a0 = A4[ar0 + k4];
        float4 a1 = A4[ar1 + k4];
        float4 a2 = A4[ar2 + k4];
        float4 a3 = A4[ar3 + k4];
        int k = k4 * 4;
        float4 b0 = W4[(size_t)(k + 0) * D4 + lane];
        float4 b1 = W4[(size_t)(k + 1) * D4 + lane];
        float4 b2 = W4[(size_t)(k + 2) * D4 + lane];
        float4 b3 = W4[(size_t)(k + 3) * D4 + lane];

        FMA4(acc0, a0.x, b0); FMA4(acc0, a0.y, b1); FMA4(acc0, a0.z, b2); FMA4(acc0, a0.w, b3);
        FMA4(acc1, a1.x, b0); FMA4(acc1, a1.y, b1); FMA4(acc1, a1.z, b2); FMA4(acc1, a1.w, b3);
        FMA4(acc2, a2.x, b0); FMA4(acc2, a2.y, b1); FMA4(acc2, a2.z, b2); FMA4(acc2, a2.w, b3);
        FMA4(acc3, a3.x, b0); FMA4(acc3, a3.y, b1); FMA4(acc3, a3.z, b2); FMA4(acc3, a3.w, b3);
    }

    if (SCALE_OUT) {
        float s0 = g_dinv[row0 + 0], s1 = g_dinv[row0 + 1];
        float s2 = g_dinv[row0 + 2], s3 = g_dinv[row0 + 3];
        acc0.x *= s0; acc0.y *= s0; acc0.z *= s0; acc0.w *= s0;
        acc1.x *= s1; acc1.y *= s1; acc1.z *= s1; acc1.w *= s1;
        acc2.x *= s2; acc2.y *= s2; acc2.z *= s2; acc2.w *= s2;
        acc3.x *= s3; acc3.y *= s3; acc3.z *= s3; acc3.w *= s3;
    }

    float4* C4 = (float4*)C;
    C4[ar0 + lane] = acc0;
    C4[ar1 + lane] = acc1;
    C4[ar2 + lane] = acc2;
    C4[ar3 + lane] = acc3;
}

// ---------------- mega kernel: GEMM1 blocks + degree-count blocks ---------
// GEMM1 is fma-bound, count is L2-atomic-bound: complementary pipes, so
// co-scheduling them in one launch overlaps ~12us of setup with GEMM1.
__global__ void k_mega(const float* __restrict__ A, const float* __restrict__ Wm,
                       float* __restrict__ C, int M,
                       const int* __restrict__ ei, int E, int gemmBlocks) {
    if ((int)blockIdx.x < gemmBlocks) {
        gemm_body<false>(blockIdx.x, threadIdx.x, A, Wm, C, M);
    } else {
        int e = (blockIdx.x - gemmBlocks) * blockDim.x + threadIdx.x;
        if (e < E) atomicAdd(&g_deg[load_idx(ei, (size_t)E + e)], 1);
    }
}

// ---------------- GEMM2 (epilogue scaled by dinv) ----------------
__global__ void k_gemm2(const float* __restrict__ A, const float* __restrict__ Wm,
                        float* __restrict__ C, int M) {
    gemm_body<true>(blockIdx.x, threadIdx.x, A, Wm, C, M);
}

// ---------------- scan of (deg-1) -> rowstart; abs cursors; dinv (fused) --
__global__ void k_scan(int n) {
    __shared__ int part[1024];
    const int tid = threadIdx.x;
    const int chunk = (n + 1023) / 1024;
    const int beg = tid * chunk;
    const int end = min(beg + chunk, n);

    int s = 0;
    for (int i = beg; i < end; ++i) s += g_deg[i] - 1;
    part[tid] = s;
    __syncthreads();

    for (int off = 1; off < 1024; off <<= 1) {
        int v = (tid >= off) ? part[tid - off] : 0;
        __syncthreads();
        part[tid] += v;
        __syncthreads();
    }

    int run = (tid > 0) ? part[tid - 1] : 0;
    for (int i = beg; i < end; ++i) {
        int dg = g_deg[i];
        g_rowstart[i] = run;
        g_cur[i] = run;                      // absolute cursor
        g_dinv[i] = rsqrtf((float)dg);
        run += dg - 1;
    }
}

// ---------------- CSR fill: src index only (1 atomic + 1 scattered 4B) ----
__global__ void k_fill(const int* __restrict__ ei, int E) {
    int e = blockIdx.x * blockDim.x + threadIdx.x;
    if (e >= E) return;
    int s = load_idx(ei, (size_t)e);
    int d = load_idx(ei, (size_t)E + e);
    int pos = atomicAdd(&g_cur[d], 1);
    g_esrc[pos] = s;
}

// ---------------- CSR aggregation + self-loop + bias + ReLU --------------
// One warp per dst node, lane owns one float4 (4 cols).
// SCALED: H rows are already pre-multiplied by dinv[src] (layer 2).
//         Otherwise multiply by dinv[src] loaded per edge (layer 1).
// out = relu( dinv[node] * (sum + selfterm) + b )
#define ADD4(acc, b) { acc.x += b.x; acc.y += b.y; acc.z += b.z; acc.w += b.w; }

template<bool SCALED>
__global__ void k_agg_csr(const float* __restrict__ H,
                          const float* __restrict__ b,
                          float* __restrict__ out, int n) {
    int warp = (int)((blockIdx.x * (size_t)blockDim.x + threadIdx.x) >> 5);
    int lane = threadIdx.x & 31;
    if (warp >= n) return;
    int node = warp;

    const float4* H4 = (const float4*)H;
    float di = g_dinv[node];

    // self-loop term: dinv[node]*H[node] (unscaled) or H'[node] (scaled)
    float4 acc = H4[(size_t)node * D4 + lane];
    if (!SCALED) { acc.x *= di; acc.y *= di; acc.z *= di; acc.w *= di; }

    int p   = g_rowstart[node];
    int end = p + (g_deg[node] - 1);

    for (; p + 3 < end; p += 4) {
        int s0 = g_esrc[p],   s1 = g_esrc[p+1];
        int s2 = g_esrc[p+2], s3 = g_esrc[p+3];
        float4 v0 = H4[(size_t)s0 * D4 + lane];
        float4 v1 = H4[(size_t)s1 * D4 + lane];
        float4 v2 = H4[(size_t)s2 * D4 + lane];
        float4 v3 = H4[(size_t)s3 * D4 + lane];
        if (SCALED) {
            ADD4(acc, v0); ADD4(acc, v1); ADD4(acc, v2); ADD4(acc, v3);
        } else {
            float n0 = g_dinv[s0], n1 = g_dinv[s1];
            float n2 = g_dinv[s2], n3 = g_dinv[s3];
            FMA4(acc, n0, v0); FMA4(acc, n1, v1);
            FMA4(acc, n2, v2); FMA4(acc, n3, v3);
        }
    }
    for (; p < end; ++p) {
        int s0 = g_esrc[p];
        float4 v0 = H4[(size_t)s0 * D4 + lane];
        if (SCALED) { ADD4(acc, v0); }
        else        { float n0 = g_dinv[s0]; FMA4(acc, n0, v0); }
    }

    float4 bv = ((const float4*)b)[lane];
    float4 r;
    r.x = fmaxf(fmaf(di, acc.x, bv.x), 0.f);
    r.y = fmaxf(fmaf(di, acc.y, bv.y), 0.f);
    r.z = fmaxf(fmaf(di, acc.z, bv.z), 0.f);
    r.w = fmaxf(fmaf(di, acc.w, bv.w), 0.f);
    ((float4*)out)[(size_t)node * D4 + lane] = r;
}

// ---------------- launch ----------------
extern "C" void kernel_launch(void* const* d_in, const int* in_sizes, int n_in,
                              void* d_out, int out_size) {
    const float* x  = (const float*)d_in[0];
    const int*   ei = (const int*)d_in[1];
    const float* W1 = (const float*)d_in[2];
    const float* b1 = (const float*)d_in[3];
    const float* W2 = (const float*)d_in[4];
    const float* b2 = (const float*)d_in[5];
    float* out = (float*)d_out;

    int n = in_sizes[0] / D;        // 50000
    int E = in_sizes[1] / 2;        // 800000

    float *h, *a;
    cudaGetSymbolAddress((void**)&h, g_h);
    cudaGetSymbolAddress((void**)&a, g_a);

    int gemmBlocks  = (n + 31) / 32;
    int countBlocks = (E + 255) / 256;
    int aggBlocks   = (n * 32 + 255) / 256;   // 1 warp per node

    // init degrees (+dtype detect)
    k_init<<<(n + 255) / 256, 256>>>(ei, n);
    // GEMM1 overlapped with degree count (independent, complementary pipes)
    k_mega<<<gemmBlocks + countBlocks, 256>>>(x, W1, h, n, ei, E, gemmBlocks);
    // rowstart + cursors + dinv
    k_scan<<<1, 1024>>>(n);
    // CSR fill (src only)
    k_fill<<<countBlocks, 256>>>(ei, E);

    // ---- layer 1: agg with per-edge dinv[s] (h is unscaled) ----
    k_agg_csr<false><<<aggBlocks, 256>>>(h, b1, a, n);

    // ---- layer 2: gemm pre-scales rows by dinv, agg is pure gather-add ----
    k_gemm2<<<gemmBlocks, 256>>>(a, W2, h, n);
    k_agg_csr<true><<<aggBlocks, 256>>>(h, b2, out, n);
}

// round 7
// speedup vs baseline: 1.1382x; 1.0580x over previous
#include <cuda_runtime.h>
#include <cuda_fp16.h>
#include <cstdint>

#define D 128
#define NMAX 50000
#define EMAX 800000
#define D4 (D/4)    // 32 float4 per fp32 row
#define DH2 (D/4)   // 32 uint2 (4 halves each) per fp16 row

// ---------------- scratch (no allocations allowed) ----------------
__device__ int    g_deg[NMAX];          // 1 + in-degree (self-loop included)
__device__ float  g_dinv[NMAX];
__device__ int    g_rowstart[NMAX];     // CSR row offsets (real edges only)
__device__ int    g_cur[NMAX];          // absolute fill cursors
__device__ int    g_esrc[EMAX];         // CSR: src node per slot
__device__ __half g_h[(size_t)NMAX * D];   // linear-transform output (fp16!)
__device__ float  g_a[(size_t)NMAX * D];   // layer-1 activation (fp32)
__device__ int    g_is64;               // 1 if edge_index is int64, 0 if int32

__device__ __forceinline__ int load_idx(const int* __restrict__ ei, size_t pos) {
    return g_is64 ? ei[2 * pos] : ei[pos];
}

__device__ __forceinline__ unsigned pack_h2(float a, float b) {
    __half2 h = __floats2half2_rn(a, b);
    return *reinterpret_cast<unsigned*>(&h);
}

// ---------------- init degrees + dtype detect (fused) ----------------
__global__ void k_init(const int* __restrict__ ei, int n) {
    int i = blockIdx.x * blockDim.x + threadIdx.x;
    if (i < n) g_deg[i] = 1;              // self-loop contributes 1
    if (blockIdx.x == 0 && threadIdx.x == 0) {
        int all0 = 1;
        for (int j = 0; j < 64; ++j)
            if (ei[2 * j + 1] != 0) { all0 = 0; break; }
        g_is64 = all0;
    }
}

// ---------------- GEMM body: fp32 A,W -> fp16 C ----------------
#define FMA4(acc, s, b) { acc.x = fmaf(s, b.x, acc.x); acc.y = fmaf(s, b.y, acc.y); \
                          acc.z = fmaf(s, b.z, acc.z); acc.w = fmaf(s, b.w, acc.w); }

template<bool SCALE_OUT>
__device__ __forceinline__ void gemm_body(int bid, int tid,
                                          const float* __restrict__ A,
                                          const float* __restrict__ Wm,
                                          __half* __restrict__ C, int M) {
    int lane = tid & 31;
    int rs   = tid >> 5;
    int row0 = bid * 32 + rs * 4;
    if (row0 >= M) return;

    const float4* A4 = (const float4*)A;
    const float4* W4 = (const float4*)Wm;

    float4 acc0 = make_float4(0,0,0,0), acc1 = acc0, acc2 = acc0, acc3 = acc0;

    size_t ar0 = (size_t)(row0 + 0) * D4;
    size_t ar1 = (size_t)(row0 + 1) * D4;
    size_t ar2 = (size_t)(row0 + 2) * D4;
    size_t ar3 = (size_t)(row0 + 3) * D4;

#pragma unroll 4
    for (int k4 = 0; k4 < D4; ++k4) {
        float4 a0 = A4[ar0 + k4];
        float4 a1 = A4[ar1 + k4];
        float4 a2 = A4[ar2 + k4];
        float4 a3 = A4[ar3 + k4];
        int k = k4 * 4;
        float4 b0 = W4[(size_t)(k + 0) * D4 + lane];
        float4 b1 = W4[(size_t)(k + 1) * D4 + lane];
        float4 b2 = W4[(size_t)(k + 2) * D4 + lane];
        float4 b3 = W4[(size_t)(k + 3) * D4 + lane];

        FMA4(acc0, a0.x, b0); FMA4(acc0, a0.y, b1); FMA4(acc0, a0.z, b2); FMA4(acc0, a0.w, b3);
        FMA4(acc1, a1.x, b0); FMA4(acc1, a1.y, b1); FMA4(acc1, a1.z, b2); FMA4(acc1, a1.w, b3);
        FMA4(acc2, a2.x, b0); FMA4(acc2, a2.y, b1); FMA4(acc2, a2.z, b2); FMA4(acc2, a2.w, b3);
        FMA4(acc3, a3.x, b0); FMA4(acc3, a3.y, b1); FMA4(acc3, a3.z, b2); FMA4(acc3, a3.w, b3);
    }

    if (SCALE_OUT) {
        float s0 = g_dinv[row0 + 0], s1 = g_dinv[row0 + 1];
        float s2 = g_dinv[row0 + 2], s3 = g_dinv[row0 + 3];
        acc0.x *= s0; acc0.y *= s0; acc0.z *= s0; acc0.w *= s0;
        acc1.x *= s1; acc1.y *= s1; acc1.z *= s1; acc1.w *= s1;
        acc2.x *= s2; acc2.y *= s2; acc2.z *= s2; acc2.w *= s2;
        acc3.x *= s3; acc3.y *= s3; acc3.z *= s3; acc3.w *= s3;
    }

    uint2* C2 = (uint2*)C;   // 4 halves per lane
    C2[(size_t)(row0 + 0) * DH2 + lane] = make_uint2(pack_h2(acc0.x, acc0.y), pack_h2(acc0.z, acc0.w));
    C2[(size_t)(row0 + 1) * DH2 + lane] = make_uint2(pack_h2(acc1.x, acc1.y), pack_h2(acc1.z, acc1.w));
    C2[(size_t)(row0 + 2) * DH2 + lane] = make_uint2(pack_h2(acc2.x, acc2.y), pack_h2(acc2.z, acc2.w));
    C2[(size_t)(row0 + 3) * DH2 + lane] = make_uint2(pack_h2(acc3.x, acc3.y), pack_h2(acc3.z, acc3.w));
}

// ---------------- mega kernel: GEMM1 blocks + degree-count blocks ---------
__global__ void k_mega(const float* __restrict__ A, const float* __restrict__ Wm,
                       __half* __restrict__ C, int M,
                       const int* __restrict__ ei, int E, int gemmBlocks) {
    if ((int)blockIdx.x < gemmBlocks) {
        gemm_body<false>(blockIdx.x, threadIdx.x, A, Wm, C, M);
    } else {
        int e = (blockIdx.x - gemmBlocks) * blockDim.x + threadIdx.x;
        if (e < E) atomicAdd(&g_deg[load_idx(ei, (size_t)E + e)], 1);
    }
}

// ---------------- GEMM2 (epilogue scaled by dinv) ----------------
__global__ void k_gemm2(const float* __restrict__ A, const float* __restrict__ Wm,
                        __half* __restrict__ C, int M) {
    gemm_body<true>(blockIdx.x, threadIdx.x, A, Wm, C, M);
}

// ---------------- scan of (deg-1) -> rowstart; abs cursors; dinv (fused) --
__global__ void k_scan(int n) {
    __shared__ int part[1024];
    const int tid = threadIdx.x;
    const int chunk = (n + 1023) / 1024;
    const int beg = tid * chunk;
    const int end = min(beg + chunk, n);

    int s = 0;
    for (int i = beg; i < end; ++i) s += g_deg[i] - 1;
    part[tid] = s;
    __syncthreads();

    for (int off = 1; off < 1024; off <<= 1) {
        int v = (tid >= off) ? part[tid - off] : 0;
        __syncthreads();
        part[tid] += v;
        __syncthreads();
    }

    int run = (tid > 0) ? part[tid - 1] : 0;
    for (int i = beg; i < end; ++i) {
        int dg = g_deg[i];
        g_rowstart[i] = run;
        g_cur[i] = run;                      // absolute cursor
        g_dinv[i] = rsqrtf((float)dg);
        run += dg - 1;
    }
}

// ---------------- CSR fill: src index only ----------------
__global__ void k_fill(const int* __restrict__ ei, int E) {
    int e = blockIdx.x * blockDim.x + threadIdx.x;
    if (e >= E) return;
    int s = load_idx(ei, (size_t)e);
    int d = load_idx(ei, (size_t)E + e);
    int pos = atomicAdd(&g_cur[d], 1);
    g_esrc[pos] = s;
}

// ---------------- CSR aggregation (fp16 gather) + bias + ReLU -------------
// One warp per dst node, lane owns 4 cols (one uint2 = 4 halves).
// SCALED: H rows pre-multiplied by dinv[src] (layer 2) -> pure add.
// out(fp32) = relu( dinv[node] * (sum + selfterm) + b )
__device__ __forceinline__ void acc_h4(float4& acc, float nm, uint2 raw) {
    __half2* ph = (__half2*)&raw;
    float2 lo = __half22float2(ph[0]);
    float2 hi = __half22float2(ph[1]);
    acc.x = fmaf(nm, lo.x, acc.x); acc.y = fmaf(nm, lo.y, acc.y);
    acc.z = fmaf(nm, hi.x, acc.z); acc.w = fmaf(nm, hi.y, acc.w);
}
__device__ __forceinline__ void add_h4(float4& acc, uint2 raw) {
    __half2* ph = (__half2*)&raw;
    float2 lo = __half22float2(ph[0]);
    float2 hi = __half22float2(ph[1]);
    acc.x += lo.x; acc.y += lo.y; acc.z += hi.x; acc.w += hi.y;
}

template<bool SCALED>
__global__ void k_agg_csr(const __half* __restrict__ H,
                          const float* __restrict__ b,
                          float* __restrict__ out, int n) {
    int warp = (int)((blockIdx.x * (size_t)blockDim.x + threadIdx.x) >> 5);
    int lane = threadIdx.x & 31;
    if (warp >= n) return;
    int node = warp;

    const uint2* H2 = (const uint2*)H;
    float di = g_dinv[node];

    // self-loop term
    float4 acc = make_float4(0, 0, 0, 0);
    {
        uint2 raw = H2[(size_t)node * DH2 + lane];
        if (SCALED) add_h4(acc, raw);
        else        acc_h4(acc, di, raw);
    }

    int p   = g_rowstart[node];
    int end = p + (g_deg[node] - 1);

    for (; p + 3 < end; p += 4) {
        int s0 = g_esrc[p],   s1 = g_esrc[p+1];
        int s2 = g_esrc[p+2], s3 = g_esrc[p+3];
        uint2 v0 = H2[(size_t)s0 * DH2 + lane];
        uint2 v1 = H2[(size_t)s1 * DH2 + lane];
        uint2 v2 = H2[(size_t)s2 * DH2 + lane];
        uint2 v3 = H2[(size_t)s3 * DH2 + lane];
        if (SCALED) {
            add_h4(acc, v0); add_h4(acc, v1); add_h4(acc, v2); add_h4(acc, v3);
        } else {
            acc_h4(acc, g_dinv[s0], v0); acc_h4(acc, g_dinv[s1], v1);
            acc_h4(acc, g_dinv[s2], v2); acc_h4(acc, g_dinv[s3], v3);
        }
    }
    for (; p < end; ++p) {
        int s0 = g_esrc[p];
        uint2 v0 = H2[(size_t)s0 * DH2 + lane];
        if (SCALED) add_h4(acc, v0);
        else        acc_h4(acc, g_dinv[s0], v0);
    }

    float4 bv = ((const float4*)b)[lane];
    float4 r;
    r.x = fmaxf(fmaf(di, acc.x, bv.x), 0.f);
    r.y = fmaxf(fmaf(di, acc.y, bv.y), 0.f);
    r.z = fmaxf(fmaf(di, acc.z, bv.z), 0.f);
    r.w = fmaxf(fmaf(di, acc.w, bv.w), 0.f);
    ((float4*)out)[(size_t)node * D4 + lane] = r;
}

// ---------------- launch ----------------
extern "C" void kernel_launch(void* const* d_in, const int* in_sizes, int n_in,
                              void* d_out, int out_size) {
    const float* x  = (const float*)d_in[0];
    const int*   ei = (const int*)d_in[1];
    const float* W1 = (const float*)d_in[2];
    const float* b1 = (const float*)d_in[3];
    const float* W2 = (const float*)d_in[4];
    const float* b2 = (const float*)d_in[5];
    float* out = (float*)d_out;

    int n = in_sizes[0] / D;        // 50000
    int E = in_sizes[1] / 2;        // 800000

    __half* h;
    float*  a;
    cudaGetSymbolAddress((void**)&h, g_h);
    cudaGetSymbolAddress((void**)&a, g_a);

    int gemmBlocks  = (n + 31) / 32;
    int countBlocks = (E + 255) / 256;
    int aggBlocks   = (n * 32 + 255) / 256;   // 1 warp per node

    // init degrees (+dtype detect)
    k_init<<<(n + 255) / 256, 256>>>(ei, n);
    // GEMM1 overlapped with degree count
    k_mega<<<gemmBlocks + countBlocks, 256>>>(x, W1, h, n, ei, E, gemmBlocks);
    // rowstart + cursors + dinv
    k_scan<<<1, 1024>>>(n);
    // CSR fill (src only)
    k_fill<<<countBlocks, 256>>>(ei, E);

    // ---- layer 1: agg with per-edge dinv[s] (h unscaled fp16) ----
    k_agg_csr<false><<<aggBlocks, 256>>>(h, b1, a, n);

    // ---- layer 2: gemm pre-scales rows by dinv -> pure fp16 gather-add ----
    k_gemm2<<<gemmBlocks, 256>>>(a, W2, h, n);
    k_agg_csr<true><<<aggBlocks, 256>>>(h, b2, out, n);
}